// round 7
// baseline (speedup 1.0000x reference)
#include <cuda_runtime.h>
#include <cuda_bf16.h>
#include <cstdint>

#define NPTS 262144
#define DPBLKS 6144   // 3*NPTS/128
#define ICBLKS 2048   // NPTS/128

// ---------------- scratch (__device__ globals; no allocation allowed) -----
__device__ float g_feats[NPTS * 8];   // [r, ux, uy, uz, inv, a, 0, 0]
__device__ float g_ic[NPTS];
__device__ float g_dp[NPTS * 3];

// Weight fragment images.
// Per MLP: 512 input-layer uint4 (bf16 k8 frags: {h0,-,l0,-}) followed by
// 3 layers * 4 k32-chunks * 16 n-tiles * 32 lanes = 6144 int8 IMMA uint4
// {wh_b0, wh_b1, wl_b0, wl_b1}.
#define ENTRIES_PER_MLP (512 + 6144)
__device__ uint4 g_Wp[2 * ENTRIES_PER_MLP];

__constant__ float c_np1[3] = {1.0f - 0.7745966692f, 1.0f, 1.0f + 0.7745966692f};

// quantization scale: +-1.0 maps exactly to +-16256 = 127*128
#define QS 16256.0f

// ---------------- math helpers --------------------------------------------
__device__ __forceinline__ float fast_tanh(float x) {
    // tanh(x) = 1 - 2/(exp(2x)+1);  ~1e-7 accurate. x->inf gives exactly 1.
    float e, r;
    asm("ex2.approx.f32 %0, %1;" : "=f"(e) : "f"(x * 2.8853900817779268f));
    asm("rcp.approx.f32 %0, %1;" : "=f"(r) : "f"(e + 1.0f));
    return fmaf(-2.0f, r, 1.0f);
}
// pack (v0 -> low bf16, v1 -> high bf16); uh = hi parts, ul = residual lo
__device__ __forceinline__ void split2(float v0, float v1, uint32_t& uh, uint32_t& ul) {
    uint32_t u;
    asm("cvt.rn.bf16x2.f32 %0, %1, %2;" : "=r"(u) : "f"(v1), "f"(v0));
    float b0 = __uint_as_float(u << 16);
    float b1 = __uint_as_float(u & 0xffff0000u);
    uh = u;
    asm("cvt.rn.bf16x2.f32 %0, %1, %2;" : "=r"(ul) : "f"(v1 - b1), "f"(v0 - b0));
}
// quantize 4 tanh outputs (|t|<=1) into packed int8 hi/lo bytes
__device__ __forceinline__ void quant4(float t0, float t1, float t2, float t3,
                                       uint32_t& vh, uint32_t& vl) {
    int q0 = __float2int_rn(t0 * QS), q1 = __float2int_rn(t1 * QS);
    int q2 = __float2int_rn(t2 * QS), q3 = __float2int_rn(t3 * QS);
    int h0 = (q0 + 64) >> 7, h1 = (q1 + 64) >> 7;
    int h2 = (q2 + 64) >> 7, h3 = (q3 + 64) >> 7;
    int l0 = q0 - (h0 << 7), l1 = q1 - (h1 << 7);
    int l2 = q2 - (h2 << 7), l3 = q3 - (h3 << 7);
    vh = (h0 & 0xff) | ((h1 & 0xff) << 8) | ((h2 & 0xff) << 16) | (h3 << 24);
    vl = (l0 & 0xff) | ((l1 & 0xff) << 8) | ((l2 & 0xff) << 16) | (l3 << 24);
}

// bf16 HMMA k8 (input layer)
__device__ __forceinline__ void mma1688(float c[4], uint32_t a0, uint32_t a1,
                                        uint32_t b0) {
    asm volatile(
        "mma.sync.aligned.m16n8k8.row.col.f32.bf16.bf16.f32 "
        "{%0,%1,%2,%3}, {%4,%5}, {%6}, {%0,%1,%2,%3};"
        : "+f"(c[0]), "+f"(c[1]), "+f"(c[2]), "+f"(c[3])
        : "r"(a0), "r"(a1), "r"(b0));
}
// int8 IMMA k32: D(16x8 s32) += A(16x32 s8) * B(32x8 s8)
__device__ __forceinline__ void imma16832(int c[4], uint32_t a0, uint32_t a1,
                                          uint32_t a2, uint32_t a3,
                                          uint32_t b0, uint32_t b1) {
    asm volatile(
        "mma.sync.aligned.m16n8k32.row.col.s32.s8.s8.s32 "
        "{%0,%1,%2,%3}, {%4,%5,%6,%7}, {%8,%9}, {%0,%1,%2,%3};"
        : "+r"(c[0]), "+r"(c[1]), "+r"(c[2]), "+r"(c[3])
        : "r"(a0), "r"(a1), "r"(a2), "r"(a3), "r"(b0), "r"(b1));
}

// ---------------- kernel 1: per-point features ----------------------------
__global__ void prep_kernel(const float4* __restrict__ tx) {
    int i = blockIdx.x * blockDim.x + threadIdx.x;
    if (i >= NPTS) return;
    float4 v = tx[i];
    float r = sqrtf(v.y * v.y + v.z * v.z + v.w * v.w);
    float rs = fmaxf(r, 1e-8f);
    float inv = 1.0f / (1.0f + r);
    float a = v.x * 0.5f;   // T0 = 0; CLIP = 1 -> min(r, max r) == r
    float* o = g_feats + i * 8;
    ((float4*)o)[0] = make_float4(r, v.y / rs, v.z / rs, v.w / rs);
    ((float4*)o)[1] = make_float4(inv, a, 0.f, 0.f);
}

// ---------------- kernel 2: pack weights ----------------------------------
// Hidden layers use a permuted k-order chosen so the next layer's int8
// A-fragments are byte-permutes of the thread's own C-fragment values:
//   k-slot s (0..31) of chunk c -> actual col 8*(4c + 2*(s>=16) + ((s&3)>>1))
//                                  + 2*(s>>2 & 3) + (s&1)
__global__ void wprep_kernel(const float* __restrict__ dp_Win,
                             const float* __restrict__ dp_Wh,
                             const float* __restrict__ ic_Win,
                             const float* __restrict__ ic_Wh) {
    int t = blockIdx.x * blockDim.x + threadIdx.x;
    if (t >= 2 * ENTRIES_PER_MLP) return;
    int m = t / ENTRIES_PER_MLP;          // 0 = dp, 1 = ic
    int e = t - m * ENTRIES_PER_MLP;
    const float* Win = m ? ic_Win : dp_Win;
    const float* Wh  = m ? ic_Wh  : dp_Wh;
    if (e < 512) {                        // input layer, bf16 k8 frags
        int J = e >> 5, lane = e & 31;
        int q = lane & 3, n = J * 8 + (lane >> 2);
        int din = m ? 5 : 6;
        int k0 = 2 * q;
        float w00 = (k0     < din) ? Win[k0 * 128 + n]       : 0.f;
        float w01 = (k0 + 1 < din) ? Win[(k0 + 1) * 128 + n] : 0.f;
        uint32_t h0, l0;
        split2(w00, w01, h0, l0);
        g_Wp[t] = make_uint4(h0, 0u, l0, 0u);
        return;
    }
    int e2 = e - 512;
    int lane = e2 & 31;
    int rest = e2 >> 5;
    int J = rest & 15; rest >>= 4;
    int c = rest & 3;
    int l = rest >> 2;                     // 0..2
    int tq = lane & 3;
    int n = J * 8 + (lane >> 2);
    const float* W = Wh + l * 16384;
    uint32_t wh[2] = {0u, 0u}, wl[2] = {0u, 0u};
#pragma unroll
    for (int half = 0; half < 2; half++) {
#pragma unroll
        for (int beta = 0; beta < 4; beta++) {
            int col = 8 * (4 * c + 2 * half + (beta >> 1)) + 2 * tq + (beta & 1);
            float w = W[col * 128 + n];
            int wq = __float2int_rn(w * QS);
            wq = max(-16256, min(16256, wq));
            int whb = (wq + 64) >> 7;
            int wlb = wq - (whb << 7);
            wh[half] |= (uint32_t)(whb & 0xff) << (beta * 8);
            wl[half] |= (uint32_t)(wlb & 0xff) << (beta * 8);
        }
    }
    g_Wp[t] = make_uint4(wh[0], wh[1], wl[0], wl[1]);
}

// ---------------- input A-fragment builder --------------------------------
__device__ __forceinline__ void build_in(bool isdp, int grow, int q,
                                         uint32_t& ah, uint32_t& al) {
    float xa, xb;
    if (isdp) {
        int p = grow / 3, nd = grow - 3 * p;
        float4 f0 = *(const float4*)(g_feats + p * 8);       // r ux uy uz
        float2 f1 = *(const float2*)(g_feats + p * 8 + 4);   // inv a
        float tt = f1.y * c_np1[nd];
        xa = (q == 0) ? tt   : (q == 1) ? f0.y : (q == 2) ? f0.w : 0.f;
        xb = (q == 0) ? f0.x : (q == 1) ? f0.z : (q == 2) ? f1.x : 0.f;
    } else {
        float4 f0 = *(const float4*)(g_feats + grow * 8);
        float2 f1 = *(const float2*)(g_feats + grow * 8 + 4);
        xa = (q == 0) ? f0.x : (q == 1) ? f0.z : (q == 2) ? f1.x : 0.f;
        xb = (q == 0) ? f0.y : (q == 1) ? f0.w : 0.f;
    }
    split2(xa, xb, ah, al);
}

// ---------------- kernel 3: int8 register-chained MLP (merged IC+DP) -------
__global__ void __launch_bounds__(256, 1) mlp_mma(
    const float* __restrict__ dp_bin, const float* __restrict__ dp_bh,
    const float* __restrict__ dp_Wout, const float* __restrict__ dp_bout,
    const float* __restrict__ ic_bin, const float* __restrict__ ic_bh,
    const float* __restrict__ ic_Wout, const float* __restrict__ ic_bout) {
    __shared__ __align__(8) float sbias[512];
    __shared__ __align__(8) float swout[128];
    const bool isdp = blockIdx.x < DPBLKS;
    const int rowblk = isdp ? blockIdx.x : (blockIdx.x - DPBLKS);
    const float* bin  = isdp ? dp_bin  : ic_bin;
    const float* bh   = isdp ? dp_bh   : ic_bh;
    const float* Wout = isdp ? dp_Wout : ic_Wout;
    const float* bout = isdp ? dp_bout : ic_bout;

    const int tid = threadIdx.x, w = tid >> 5, lane = tid & 31;
    const int q = lane & 3, nr = lane >> 2;

    if (tid < 128) {
        sbias[tid]       = bin[tid];
        sbias[128 + tid] = bh[tid];
        sbias[256 + tid] = bh[128 + tid];
        sbias[384 + tid] = bh[256 + tid];
        swout[tid]       = Wout[tid];
    }
    __syncthreads();

    const int r0 = rowblk * 128 + w * 16 + nr;
    const uint4* __restrict__ Bp = g_Wp + (isdp ? 0 : 1) * ENTRIES_PER_MLP;

    // recombination constants: z = K1*C1 + K2*C2
    const float K1 = (float)(16384.0 / ((double)QS * (double)QS));
    const float K2 = (float)(128.0 / ((double)QS * (double)QS));

    uint32_t Vh[16], Vl[16];   // packed int8 activations {r0c0,r0c1,r8c0,r8c1}

    // ---- input layer (bf16 k8) + first epilogue -> Vh/Vl ----
    {
        uint32_t a0h, a0l, a1h, a1l;
        build_in(isdp, r0, q, a0h, a0l);
        build_in(isdp, r0 + 8, q, a1h, a1l);
        float Cf[16][4];
#pragma unroll
        for (int j = 0; j < 16; j++) {
            uint4 b = __ldg(&Bp[j * 32 + lane]);
            Cf[j][0] = 0.f; Cf[j][1] = 0.f; Cf[j][2] = 0.f; Cf[j][3] = 0.f;
            mma1688(Cf[j], a0h, a1h, b.x);
            mma1688(Cf[j], a0h, a1h, b.z);
            mma1688(Cf[j], a0l, a1l, b.x);
        }
#pragma unroll
        for (int j = 0; j < 16; j++) {
            float2 bb = *(const float2*)(sbias + j * 8 + 2 * q);
            quant4(fast_tanh(Cf[j][0] + bb.x), fast_tanh(Cf[j][1] + bb.y),
                   fast_tanh(Cf[j][2] + bb.x), fast_tanh(Cf[j][3] + bb.y),
                   Vh[j], Vl[j]);
        }
    }

    int C1[16][4], C2[16][4];
    // ---- 3 hidden layers: int8 IMMA ----
#pragma unroll 1
    for (int e = 0; e < 3; e++) {
#pragma unroll
        for (int j = 0; j < 16; j++) {
            C1[j][0] = 0; C1[j][1] = 0; C1[j][2] = 0; C1[j][3] = 0;
            C2[j][0] = 0; C2[j][1] = 0; C2[j][2] = 0; C2[j][3] = 0;
        }
        const uint4* __restrict__ BL = Bp + 512 + e * 2048;
#pragma unroll
        for (int c = 0; c < 4; c++) {
            // A-frags: pure byte-permutes of this thread's own packed values
            uint32_t ah0 = __byte_perm(Vh[4 * c + 0], Vh[4 * c + 1], 0x5410);
            uint32_t ah1 = __byte_perm(Vh[4 * c + 0], Vh[4 * c + 1], 0x7632);
            uint32_t ah2 = __byte_perm(Vh[4 * c + 2], Vh[4 * c + 3], 0x5410);
            uint32_t ah3 = __byte_perm(Vh[4 * c + 2], Vh[4 * c + 3], 0x7632);
            uint32_t al0 = __byte_perm(Vl[4 * c + 0], Vl[4 * c + 1], 0x5410);
            uint32_t al1 = __byte_perm(Vl[4 * c + 0], Vl[4 * c + 1], 0x7632);
            uint32_t al2 = __byte_perm(Vl[4 * c + 2], Vl[4 * c + 3], 0x5410);
            uint32_t al3 = __byte_perm(Vl[4 * c + 2], Vl[4 * c + 3], 0x7632);
            const uint4* bp = &BL[c * 16 * 32 + lane];
#pragma unroll
            for (int J = 0; J < 16; J += 2) {
                uint4 b0 = __ldg(bp + J * 32);
                uint4 b1 = __ldg(bp + (J + 1) * 32);
                imma16832(C1[J],     ah0, ah1, ah2, ah3, b0.x, b0.y);
                imma16832(C1[J + 1], ah0, ah1, ah2, ah3, b1.x, b1.y);
                imma16832(C2[J],     ah0, ah1, ah2, ah3, b0.z, b0.w);
                imma16832(C2[J + 1], ah0, ah1, ah2, ah3, b1.z, b1.w);
                imma16832(C2[J],     al0, al1, al2, al3, b0.x, b0.y);
                imma16832(C2[J + 1], al0, al1, al2, al3, b1.x, b1.y);
            }
        }
        if (e < 2) {
            // epilogue: recombine + bias + tanh + requantize
#pragma unroll
            for (int j = 0; j < 16; j++) {
                float2 bb = *(const float2*)(sbias + (e + 1) * 128 + j * 8 + 2 * q);
                float z0 = fmaf((float)C1[j][0], K1, fmaf((float)C2[j][0], K2, bb.x));
                float z1 = fmaf((float)C1[j][1], K1, fmaf((float)C2[j][1], K2, bb.y));
                float z2 = fmaf((float)C1[j][2], K1, fmaf((float)C2[j][2], K2, bb.x));
                float z3 = fmaf((float)C1[j][3], K1, fmaf((float)C2[j][3], K2, bb.y));
                quant4(fast_tanh(z0), fast_tanh(z1), fast_tanh(z2), fast_tanh(z3),
                       Vh[j], Vl[j]);
            }
        }
    }

    // ---- final: recombine + bias + tanh + dot(Wout) + quad reduce ----
    float s0 = 0.f, s1 = 0.f;
#pragma unroll
    for (int j = 0; j < 16; j++) {
        float2 bb = *(const float2*)(sbias + 384 + j * 8 + 2 * q);
        float2 ww = *(const float2*)(swout + j * 8 + 2 * q);
        float z0 = fmaf((float)C1[j][0], K1, fmaf((float)C2[j][0], K2, bb.x));
        float z1 = fmaf((float)C1[j][1], K1, fmaf((float)C2[j][1], K2, bb.y));
        float z2 = fmaf((float)C1[j][2], K1, fmaf((float)C2[j][2], K2, bb.x));
        float z3 = fmaf((float)C1[j][3], K1, fmaf((float)C2[j][3], K2, bb.y));
        s0 = fmaf(fast_tanh(z0), ww.x, s0);
        s0 = fmaf(fast_tanh(z1), ww.y, s0);
        s1 = fmaf(fast_tanh(z2), ww.x, s1);
        s1 = fmaf(fast_tanh(z3), ww.y, s1);
    }
    s0 += __shfl_xor_sync(0xffffffffu, s0, 1);
    s0 += __shfl_xor_sync(0xffffffffu, s0, 2);
    s1 += __shfl_xor_sync(0xffffffffu, s1, 1);
    s1 += __shfl_xor_sync(0xffffffffu, s1, 2);
    if (q == 0) {
        float bo = __ldg(bout);
        float* gout = isdp ? g_dp : g_ic;
        gout[r0]     = s0 + bo;
        gout[r0 + 8] = s1 + bo;
    }
}

// ---------------- kernel 4: GL quadrature + final scaling ------------------
__global__ void combine_kernel(float* __restrict__ out) {
    int i = blockIdx.x * blockDim.x + threadIdx.x;
    if (i >= NPTS) return;
    const float* f = g_feats + i * 8;
    float a = f[5], inv = f[4];
    const float w0 = (float)(5.0 / 9.0), w1 = (float)(8.0 / 9.0);
    float s = w0 * g_dp[3 * i] + w1 * g_dp[3 * i + 1] + w0 * g_dp[3 * i + 2];
    out[i] = (g_ic[i] + a * s) * inv;
}

// ---------------- host launcher --------------------------------------------
extern "C" void kernel_launch(void* const* d_in, const int* in_sizes, int n_in,
                              void* d_out, int out_size) {
    const float* tx      = (const float*)d_in[0];
    const float* dp_Win  = (const float*)d_in[1];
    const float* dp_bin  = (const float*)d_in[2];
    const float* dp_Wh   = (const float*)d_in[3];
    const float* dp_bh   = (const float*)d_in[4];
    const float* dp_Wout = (const float*)d_in[5];
    const float* dp_bout = (const float*)d_in[6];
    const float* ic_Win  = (const float*)d_in[7];
    const float* ic_bin  = (const float*)d_in[8];
    const float* ic_Wh   = (const float*)d_in[9];
    const float* ic_bh   = (const float*)d_in[10];
    const float* ic_Wout = (const float*)d_in[11];
    const float* ic_bout = (const float*)d_in[12];
    float* out = (float*)d_out;

    prep_kernel<<<NPTS / 256, 256>>>((const float4*)tx);
    wprep_kernel<<<(2 * ENTRIES_PER_MLP + 255) / 256, 256>>>(dp_Win, dp_Wh,
                                                             ic_Win, ic_Wh);
    mlp_mma<<<DPBLKS + ICBLKS, 256>>>(dp_bin, dp_bh, dp_Wout, dp_bout,
                                      ic_bin, ic_bh, ic_Wout, ic_bout);
    combine_kernel<<<NPTS / 256, 256>>>(out);
}

// round 8
// speedup vs baseline: 2.3436x; 2.3436x over previous
#include <cuda_runtime.h>
#include <cuda_bf16.h>
#include <cstdint>

#define NPTS 262144
#define DPBLKS 12288   // 3*NPTS/64
#define ICBLKS 4096    // NPTS/64

// ---------------- scratch (__device__ globals; no allocation allowed) -----
__device__ float g_feats[NPTS * 8];   // [r, ux, uy, uz, inv, a, 0, 0]
__device__ float g_ic[NPTS];
__device__ float g_dp[NPTS * 3];

// Pre-packed B fragments for mma.m16n8k16: one uint4 {h0,h1,l0,l1} per lane
// per frag. Per MLP: 25 ksteps (1 input + 3 layers * 8) x 16 nfrags x 32 lanes.
#define FRAGS_PER_MLP (25 * 16 * 32)   // 12800 uint4
__device__ uint4 g_Wp[2 * FRAGS_PER_MLP];

__constant__ float c_np1[3] = {1.0f - 0.7745966692f, 1.0f, 1.0f + 0.7745966692f};

// ---------------- math helpers --------------------------------------------
__device__ __forceinline__ float fast_tanh(float x) {
    // tanh(x) = 1 - 2/(exp(2x)+1);  ~1e-7 accurate
    float e, r;
    asm("ex2.approx.f32 %0, %1;" : "=f"(e) : "f"(x * 2.8853900817779268f));
    asm("rcp.approx.f32 %0, %1;" : "=f"(r) : "f"(e + 1.0f));
    return fmaf(-2.0f, r, 1.0f);
}
// pack (v0 -> low bf16, v1 -> high bf16); uh = hi parts, ul = residual lo
__device__ __forceinline__ void split2(float v0, float v1, uint32_t& uh, uint32_t& ul) {
    uint32_t u;
    asm("cvt.rn.bf16x2.f32 %0, %1, %2;" : "=r"(u) : "f"(v1), "f"(v0));
    float b0 = __uint_as_float(u << 16);
    float b1 = __uint_as_float(u & 0xffff0000u);
    uh = u;
    asm("cvt.rn.bf16x2.f32 %0, %1, %2;" : "=r"(ul) : "f"(v1 - b1), "f"(v0 - b0));
}

// bf16 HMMA k16: D(16x8) += A(16x16) * B(16x8), fp32 accum
__device__ __forceinline__ void mma16816(float c[4], uint32_t a0, uint32_t a1,
                                         uint32_t a2, uint32_t a3,
                                         uint32_t b0, uint32_t b1) {
    asm volatile(
        "mma.sync.aligned.m16n8k16.row.col.f32.bf16.bf16.f32 "
        "{%0,%1,%2,%3}, {%4,%5,%6,%7}, {%8,%9}, {%0,%1,%2,%3};"
        : "+f"(c[0]), "+f"(c[1]), "+f"(c[2]), "+f"(c[3])
        : "r"(a0), "r"(a1), "r"(a2), "r"(a3), "r"(b0), "r"(b1));
}
// bf16 HMMA k8 (input layer)
__device__ __forceinline__ void mma1688(float c[4], uint32_t a0, uint32_t a1,
                                        uint32_t b0) {
    asm volatile(
        "mma.sync.aligned.m16n8k8.row.col.f32.bf16.bf16.f32 "
        "{%0,%1,%2,%3}, {%4,%5}, {%6}, {%0,%1,%2,%3};"
        : "+f"(c[0]), "+f"(c[1]), "+f"(c[2]), "+f"(c[3])
        : "r"(a0), "r"(a1), "r"(b0));
}

// ---------------- kernel 1: per-point features ----------------------------
__global__ void prep_kernel(const float4* __restrict__ tx) {
    int i = blockIdx.x * blockDim.x + threadIdx.x;
    if (i >= NPTS) return;
    float4 v = tx[i];
    float r = sqrtf(v.y * v.y + v.z * v.z + v.w * v.w);
    float rs = fmaxf(r, 1e-8f);
    float inv = 1.0f / (1.0f + r);
    float a = v.x * 0.5f;   // T0 = 0; CLIP = 1 -> min(r, max r) == r
    float* o = g_feats + i * 8;
    ((float4*)o)[0] = make_float4(r, v.y / rs, v.z / rs, v.w / rs);
    ((float4*)o)[1] = make_float4(inv, a, 0.f, 0.f);
}

// ---------------- kernel 2: pack weights into B-fragment layout ------------
__global__ void wprep_kernel(const float* __restrict__ dp_Win,
                             const float* __restrict__ dp_Wh,
                             const float* __restrict__ ic_Win,
                             const float* __restrict__ ic_Wh) {
    int t = blockIdx.x * blockDim.x + threadIdx.x;
    if (t >= 2 * FRAGS_PER_MLP) return;
    int lane = t & 31;
    int g = t >> 5;                // 0..799
    int m = g / 400;               // 0 = dp, 1 = ic
    int gg = g - m * 400;
    int ks = gg >> 4;              // 0 = input layer, 1..24 = hidden
    int j = gg & 15;
    const float* Win = m ? ic_Win : dp_Win;
    const float* Wh  = m ? ic_Wh  : dp_Wh;
    int din = m ? 5 : 6;
    int q = lane & 3;
    int n = j * 8 + (lane >> 2);
    float w00, w01, w10, w11;
    if (ks == 0) {
        int k0 = 2 * q;
        w00 = (k0     < din) ? Win[k0 * 128 + n]       : 0.f;
        w01 = (k0 + 1 < din) ? Win[(k0 + 1) * 128 + n] : 0.f;
        w10 = 0.f; w11 = 0.f;
    } else {
        int l = (ks - 1) >> 3, s = (ks - 1) & 7;
        int kb = 16 * s + 2 * q;
        const float* W = Wh + l * 16384;
        w00 = W[kb * 128 + n];       w01 = W[(kb + 1) * 128 + n];
        w10 = W[(kb + 8) * 128 + n]; w11 = W[(kb + 9) * 128 + n];
    }
    uint32_t h0, l0, h1, l1;
    split2(w00, w01, h0, l0);
    split2(w10, w11, h1, l1);
    g_Wp[t] = make_uint4(h0, h1, l0, l1);
}

// ---------------- input A-fragment builder --------------------------------
__device__ __forceinline__ void build_in(bool isdp, int grow, int q,
                                         uint32_t& ah, uint32_t& al) {
    float xa, xb;
    if (isdp) {
        int p = grow / 3, nd = grow - 3 * p;
        float4 f0 = *(const float4*)(g_feats + p * 8);       // r ux uy uz
        float2 f1 = *(const float2*)(g_feats + p * 8 + 4);   // inv a
        float tt = f1.y * c_np1[nd];
        xa = (q == 0) ? tt   : (q == 1) ? f0.y : (q == 2) ? f0.w : 0.f;
        xb = (q == 0) ? f0.x : (q == 1) ? f0.z : (q == 2) ? f1.x : 0.f;
    } else {
        float4 f0 = *(const float4*)(g_feats + grow * 8);
        float2 f1 = *(const float2*)(g_feats + grow * 8 + 4);
        xa = (q == 0) ? f0.x : (q == 1) ? f0.z : (q == 2) ? f1.x : 0.f;
        xb = (q == 0) ? f0.y : (q == 1) ? f0.w : 0.f;
    }
    split2(xa, xb, ah, al);
}

// ---------------- kernel 3: split-N HMMA MLP with SMEM activation exchange -
// CTA = 256 threads = 8 warps; CTA covers 64 rows x 128 cols.
// Warp w: row-group rg = w&3 (16 rows), col-group cg = w>>2 (64 cols, 8 n8
// tiles). Activations H go through SMEM each layer (packed {hi,lo} bf16x2),
// A-fragments are loaded just-in-time per k-chunk. Low regs -> 2 CTAs/SM
// -> 4 warps/SMSP so MMA and epilogue phases of different warps overlap.
__global__ void __launch_bounds__(256, 2) mlp_mma(
    const float* __restrict__ dp_bin, const float* __restrict__ dp_bh,
    const float* __restrict__ dp_Wout, const float* __restrict__ dp_bout,
    const float* __restrict__ ic_bin, const float* __restrict__ ic_bh,
    const float* __restrict__ ic_Wout, const float* __restrict__ ic_bout) {
    __shared__ uint2 sH[64][65];       // [row][colpair] = {hi bf16x2, lo bf16x2}
    __shared__ __align__(8) float sbias[512];
    __shared__ __align__(8) float swout[128];
    __shared__ float sred[64];

    const bool isdp = blockIdx.x < DPBLKS;
    const int rowblk = isdp ? blockIdx.x : (blockIdx.x - DPBLKS);
    const float* bin  = isdp ? dp_bin  : ic_bin;
    const float* bh   = isdp ? dp_bh   : ic_bh;
    const float* Wout = isdp ? dp_Wout : ic_Wout;
    const float* bout = isdp ? dp_bout : ic_bout;

    const int tid = threadIdx.x, w = tid >> 5, lane = tid & 31;
    const int rg = w & 3, cg = w >> 2;
    const int q = lane & 3, lr = lane >> 2;
    const int rr0 = rg * 16 + lr;              // CTA-relative rows rr0, rr0+8
    const int colb = cg * 64 + 2 * q;          // this thread's col base in half

    if (tid < 128) {
        sbias[tid]       = bin[tid];
        sbias[128 + tid] = bh[tid];
        sbias[256 + tid] = bh[128 + tid];
        sbias[384 + tid] = bh[256 + tid];
        swout[tid]       = Wout[tid];
    }
    __syncthreads();

    const int r0 = rowblk * 64 + rr0;          // global rows r0, r0+8
    const uint4* __restrict__ Bp = g_Wp + (isdp ? 0 : 1) * FRAGS_PER_MLP;

    float C[8][4];
    // ---- input layer (k8), 8 n-tiles of this col half ----
    {
        uint32_t a0h, a0l, a1h, a1l;
        build_in(isdp, r0, q, a0h, a0l);
        build_in(isdp, r0 + 8, q, a1h, a1l);
#pragma unroll
        for (int j = 0; j < 8; j++) {
            uint4 b = __ldg(&Bp[(cg * 8 + j) * 32 + lane]);
            C[j][0] = 0.f; C[j][1] = 0.f; C[j][2] = 0.f; C[j][3] = 0.f;
            mma1688(C[j], a0h, a1h, b.x);
            mma1688(C[j], a0h, a1h, b.z);
            mma1688(C[j], a0l, a1l, b.x);
        }
    }

    // ---- 3 hidden layers ----
#pragma unroll 1
    for (int e = 0; e < 3; e++) {
        // epilogue: bias + tanh + split-pack -> SMEM
#pragma unroll
        for (int j = 0; j < 8; j++) {
            float2 bb = *(const float2*)(sbias + e * 128 + colb + 8 * j);
            float t0 = fast_tanh(C[j][0] + bb.x);
            float t1 = fast_tanh(C[j][1] + bb.y);
            float t2 = fast_tanh(C[j][2] + bb.x);
            float t3 = fast_tanh(C[j][3] + bb.y);
            uint32_t uh, ul;
            int widx = cg * 32 + 4 * j + q;
            split2(t0, t1, uh, ul);
            sH[rr0][widx] = make_uint2(uh, ul);
            split2(t2, t3, uh, ul);
            sH[rr0 + 8][widx] = make_uint2(uh, ul);
        }
        __syncthreads();
#pragma unroll
        for (int j = 0; j < 8; j++) {
            C[j][0] = 0.f; C[j][1] = 0.f; C[j][2] = 0.f; C[j][3] = 0.f;
        }
        const uint4* __restrict__ BL = Bp + (1 + e * 8) * 512;
#pragma unroll
        for (int s = 0; s < 8; s++) {
            uint2 A0 = sH[rr0][8 * s + q];
            uint2 A1 = sH[rr0 + 8][8 * s + q];
            uint2 A2 = sH[rr0][8 * s + 4 + q];
            uint2 A3 = sH[rr0 + 8][8 * s + 4 + q];
            const uint4* bp = &BL[(s * 16 + cg * 8) * 32 + lane];
#pragma unroll
            for (int j = 0; j < 8; j++) {
                uint4 b = __ldg(bp + j * 32);
                mma16816(C[j], A0.x, A1.x, A2.x, A3.x, b.x, b.y);
                mma16816(C[j], A0.x, A1.x, A2.x, A3.x, b.z, b.w);
                mma16816(C[j], A0.y, A1.y, A2.y, A3.y, b.x, b.y);
            }
        }
        __syncthreads();   // all A reads done before next epilogue overwrites
    }

    // ---- final: bias + tanh + dot(Wout) + reduce ----
    float s0 = 0.f, s1 = 0.f;
#pragma unroll
    for (int j = 0; j < 8; j++) {
        float2 bb = *(const float2*)(sbias + 384 + colb + 8 * j);
        float2 ww = *(const float2*)(swout + colb + 8 * j);
        s0 = fmaf(fast_tanh(C[j][0] + bb.x), ww.x, s0);
        s0 = fmaf(fast_tanh(C[j][1] + bb.y), ww.y, s0);
        s1 = fmaf(fast_tanh(C[j][2] + bb.x), ww.x, s1);
        s1 = fmaf(fast_tanh(C[j][3] + bb.y), ww.y, s1);
    }
    s0 += __shfl_xor_sync(0xffffffffu, s0, 1);
    s0 += __shfl_xor_sync(0xffffffffu, s0, 2);
    s1 += __shfl_xor_sync(0xffffffffu, s1, 1);
    s1 += __shfl_xor_sync(0xffffffffu, s1, 2);
    if (cg == 1 && q == 0) {
        sred[rr0]     = s0;
        sred[rr0 + 8] = s1;
    }
    __syncthreads();
    if (cg == 0 && q == 0) {
        float bo = __ldg(bout);
        float* gout = isdp ? g_dp : g_ic;
        gout[r0]     = s0 + sred[rr0]     + bo;
        gout[r0 + 8] = s1 + sred[rr0 + 8] + bo;
    }
}

// ---------------- kernel 4: GL quadrature + final scaling ------------------
__global__ void combine_kernel(float* __restrict__ out) {
    int i = blockIdx.x * blockDim.x + threadIdx.x;
    if (i >= NPTS) return;
    const float* f = g_feats + i * 8;
    float a = f[5], inv = f[4];
    const float w0 = (float)(5.0 / 9.0), w1 = (float)(8.0 / 9.0);
    float s = w0 * g_dp[3 * i] + w1 * g_dp[3 * i + 1] + w0 * g_dp[3 * i + 2];
    out[i] = (g_ic[i] + a * s) * inv;
}

// ---------------- host launcher --------------------------------------------
extern "C" void kernel_launch(void* const* d_in, const int* in_sizes, int n_in,
                              void* d_out, int out_size) {
    const float* tx      = (const float*)d_in[0];
    const float* dp_Win  = (const float*)d_in[1];
    const float* dp_bin  = (const float*)d_in[2];
    const float* dp_Wh   = (const float*)d_in[3];
    const float* dp_bh   = (const float*)d_in[4];
    const float* dp_Wout = (const float*)d_in[5];
    const float* dp_bout = (const float*)d_in[6];
    const float* ic_Win  = (const float*)d_in[7];
    const float* ic_bin  = (const float*)d_in[8];
    const float* ic_Wh   = (const float*)d_in[9];
    const float* ic_bh   = (const float*)d_in[10];
    const float* ic_Wout = (const float*)d_in[11];
    const float* ic_bout = (const float*)d_in[12];
    float* out = (float*)d_out;

    prep_kernel<<<NPTS / 256, 256>>>((const float4*)tx);
    wprep_kernel<<<(2 * FRAGS_PER_MLP + 255) / 256, 256>>>(dp_Win, dp_Wh,
                                                           ic_Win, ic_Wh);
    mlp_mma<<<DPBLKS + ICBLKS, 256>>>(dp_bin, dp_bh, dp_Wout, dp_bout,
                                      ic_bin, ic_bh, ic_Wout, ic_bout);
    combine_kernel<<<NPTS / 256, 256>>>(out);
}